// round 1
// baseline (speedup 1.0000x reference)
#include <cuda_runtime.h>
#include <math.h>

#define BATCH 4
#define LSEQ 513
#define MTOK (BATCH*LSEQ)      // 2052
#define DM 768
#define DI 1536
#define DSN 16
#define DTRK 48
#define NDEPTH 24
#define NPATCH 512
#define PDIM 256

// ---------------- scratch (device globals; no allocation allowed) ----------
__device__ float g_h  [MTOK*DM];
__device__ float g_res[MTOK*DM];
__device__ float g_xn [MTOK*DM];
__device__ float g_xz [MTOK*2*DI];
__device__ float g_c  [2][MTOK*DI];
__device__ float g_dbl[2][MTOK*80];
__device__ float g_dt [2][MTOK*DI];
__device__ float g_y  [MTOK*DI];
__device__ float g_xp [BATCH*NPATCH*PDIM];
__device__ float g_ptok[BATCH*NPATCH*DM];

__device__ __forceinline__ float siluf(float x){ return x / (1.f + __expf(-x)); }

// ---------------- generic fp32 GEMM:  C[M,N] = A[M,K] * B[N,K]^T ----------
// row-major A (lda), row-major B (ldb, i.e. B stored as N x K), row-major C.
// Requires K % 16 == 0, lda/ldb % 4 == 0.
__global__ __launch_bounds__(256)
void gemm_nt(const float* __restrict__ A, int lda,
             const float* __restrict__ B, int ldb,
             float* __restrict__ C, int ldc,
             int M, int N, int K)
{
    __shared__ float As[16][128];
    __shared__ float Bs[16][128];
    const int tid = threadIdx.x;
    const int tx = tid & 15;          // 0..15  -> col group
    const int ty = tid >> 4;          // 0..15  -> row group
    const int rowBase = blockIdx.y * 128;
    const int colBase = blockIdx.x * 128;

    float acc[8][8];
#pragma unroll
    for (int i = 0; i < 8; i++)
#pragma unroll
        for (int j = 0; j < 8; j++) acc[i][j] = 0.f;

    for (int k0 = 0; k0 < K; k0 += 16) {
#pragma unroll
        for (int it = 0; it < 2; it++) {
            int f  = tid + it * 256;          // 0..511
            int r  = f >> 2;                  // 0..127
            int kq = (f & 3) * 4;             // 0,4,8,12
            int gr = rowBase + r;
            float4 v = make_float4(0.f,0.f,0.f,0.f);
            if (gr < M) v = *(const float4*)&A[(size_t)gr*lda + k0 + kq];
            As[kq+0][r]=v.x; As[kq+1][r]=v.y; As[kq+2][r]=v.z; As[kq+3][r]=v.w;
        }
#pragma unroll
        for (int it = 0; it < 2; it++) {
            int f  = tid + it * 256;
            int r  = f >> 2;
            int kq = (f & 3) * 4;
            int gc = colBase + r;
            float4 v = make_float4(0.f,0.f,0.f,0.f);
            if (gc < N) v = *(const float4*)&B[(size_t)gc*ldb + k0 + kq];
            Bs[kq+0][r]=v.x; Bs[kq+1][r]=v.y; Bs[kq+2][r]=v.z; Bs[kq+3][r]=v.w;
        }
        __syncthreads();
#pragma unroll
        for (int kk = 0; kk < 16; kk++) {
            float a[8], b[8];
            *(float4*)&a[0] = *(float4*)&As[kk][ty*8];
            *(float4*)&a[4] = *(float4*)&As[kk][ty*8+4];
            *(float4*)&b[0] = *(float4*)&Bs[kk][tx*8];
            *(float4*)&b[4] = *(float4*)&Bs[kk][tx*8+4];
#pragma unroll
            for (int i = 0; i < 8; i++)
#pragma unroll
                for (int j = 0; j < 8; j++)
                    acc[i][j] = fmaf(a[i], b[j], acc[i][j]);
        }
        __syncthreads();
    }
#pragma unroll
    for (int i = 0; i < 8; i++) {
        int r = rowBase + ty*8 + i;
        if (r >= M) continue;
#pragma unroll
        for (int j = 0; j < 8; j++) {
            int c = colBase + tx*8 + j;
            if (c < N) C[(size_t)r*ldc + c] = acc[i][j];
        }
    }
}

// ---------------- patchify: x(4,128,1024) -> xp(4,512,256) ----------------
__global__ void k_patchify(const float* __restrict__ x)
{
    int idx = blockIdx.x * blockDim.x + threadIdx.x;
    if (idx >= BATCH*NPATCH*PDIM) return;
    int i  = idx & 255;
    int p  = (idx >> 8) & 511;
    int b  = idx >> 17;
    int pr = i >> 4, pc = i & 15;
    int f  = p >> 6, t = p & 63;
    g_xp[idx] = x[((size_t)b*128 + f*16 + pr)*1024 + t*16 + pc];
}

// ---------------- assemble tokens: cls + patch_b + pos; res = 0 ----------
__global__ void k_assemble(const float* __restrict__ patch_b,
                           const float* __restrict__ cls,
                           const float* __restrict__ pos)
{
    int idx = blockIdx.x * blockDim.x + threadIdx.x;
    if (idx >= MTOK*DM) return;
    int n = idx % DM;
    int l = (idx / DM) % LSEQ;
    int b = idx / (DM*LSEQ);
    float v;
    if (l == 0) v = cls[n];
    else        v = g_ptok[((size_t)b*NPATCH + (l-1))*DM + n] + patch_b[n];
    v += pos[(size_t)l*DM + n];
    g_h[idx] = v;
    g_res[idx] = 0.f;
}

// ---------------- res += h;  xn = rmsnorm(res) * ln_w --------------------
__global__ __launch_bounds__(256)
void k_prenorm(const float* __restrict__ ln_w, int layer)
{
    int m = blockIdx.x;
    int tid = threadIdx.x;
    __shared__ float red[256];
    size_t base = (size_t)m * DM;
    float v[3]; float ss = 0.f;
#pragma unroll
    for (int i = 0; i < 3; i++) {
        int n = tid + i*256;
        float t = g_res[base+n] + g_h[base+n];
        v[i] = t; g_res[base+n] = t; ss += t*t;
    }
    red[tid] = ss; __syncthreads();
    for (int o = 128; o > 0; o >>= 1) { if (tid < o) red[tid] += red[tid+o]; __syncthreads(); }
    float scale = rsqrtf(red[0] / (float)DM + 1e-5f);
#pragma unroll
    for (int i = 0; i < 3; i++) {
        int n = tid + i*256;
        g_xn[base+n] = v[i] * scale * ln_w[(size_t)layer*DM + n];
    }
}

// ---------------- causal depthwise conv + silu (both branches) ------------
__global__ void k_conv(const float* __restrict__ conv_w,
                       const float* __restrict__ conv_b, int layer)
{
    int idx = blockIdx.x * blockDim.x + threadIdx.x;
    if (idx >= BATCH*LSEQ*DI) return;
    int d = idx % DI;
    int t = (idx / DI) % LSEQ;
    int b = idx / (DI*LSEQ);

    const float* w0 = conv_w + ((size_t)(layer*2+0)*DI + d)*4;
    const float* w1 = conv_w + ((size_t)(layer*2+1)*DI + d)*4;
    float acc0 = conv_b[(size_t)(layer*2+0)*DI + d];
    float acc1 = conv_b[(size_t)(layer*2+1)*DI + d];
#pragma unroll
    for (int k = 0; k < 4; k++) {
        int tt = t - 3 + k;
        if (tt >= 0) {
            acc0 = fmaf(w0[k], g_xz[((size_t)b*LSEQ + tt)*(2*DI) + d], acc0);
            acc1 = fmaf(w1[k], g_xz[((size_t)b*LSEQ + (LSEQ-1-tt))*(2*DI) + d], acc1);
        }
    }
    size_t o = ((size_t)b*LSEQ + t)*DI + d;
    g_c[0][o] = siluf(acc0);
    g_c[1][o] = siluf(acc1);
}

// ---------------- skinny GEMM: dbl[br][m,80] = c[br][m,:] @ w_x^T ---------
__global__ __launch_bounds__(256)
void k_gemm_x(const float* __restrict__ w_x, int layer)
{
    int br = blockIdx.y;
    int m0 = blockIdx.x * 16;
    int tid = threadIdx.x;
    int tx = tid & 15, ty = tid >> 4;
    __shared__ float As[16][33];
    __shared__ float Bs[80][33];
    const float* B = w_x + (size_t)(layer*2+br)*80*DI;

    float acc[5] = {0.f,0.f,0.f,0.f,0.f};
    for (int k0 = 0; k0 < DI; k0 += 32) {
        {   // A: 16 x 32
            int f = tid * 2;
            int r = f >> 5, kk = f & 31;
            int gm = m0 + r;
            float2 v = make_float2(0.f, 0.f);
            if (gm < MTOK) v = *(const float2*)&g_c[br][(size_t)gm*DI + k0 + kk];
            As[r][kk] = v.x; As[r][kk+1] = v.y;
        }
#pragma unroll
        for (int i = 0; i < 10; i++) {   // B: 80 x 32
            int e = tid + i*256;
            int r = e >> 5, kk = e & 31;
            Bs[r][kk] = B[(size_t)r*DI + k0 + kk];
        }
        __syncthreads();
#pragma unroll
        for (int kk = 0; kk < 32; kk++) {
            float a = As[ty][kk];
#pragma unroll
            for (int j = 0; j < 5; j++)
                acc[j] = fmaf(a, Bs[tx + 16*j][kk], acc[j]);
        }
        __syncthreads();
    }
    int gm = m0 + ty;
    if (gm < MTOK)
#pragma unroll
        for (int j = 0; j < 5; j++)
            g_dbl[br][(size_t)gm*80 + tx + 16*j] = acc[j];
}

// ---------------- dt bias + softplus (in place on g_dt) -------------------
__global__ void k_softplus(const float* __restrict__ b_dt, int layer)
{
    int br = blockIdx.y;
    int idx = blockIdx.x * blockDim.x + threadIdx.x;
    if (idx >= MTOK*DI) return;
    int d = idx % DI;
    float x = g_dt[br][idx] + b_dt[(size_t)(layer*2+br)*DI + d];
    g_dt[br][idx] = (x > 20.f) ? x : log1pf(__expf(x));
}

// ---------------- selective scan (sequential over t), writes into g_c -----
__global__ __launch_bounds__(128)
void k_scan(const float* __restrict__ a_log,
            const float* __restrict__ dd, int layer)
{
    int br = blockIdx.z;
    int b  = blockIdx.y;
    int d  = blockIdx.x * 128 + threadIdx.x;

    const float* al = a_log + ((size_t)(layer*2+br)*DI + d)*DSN;
    float A[DSN];
#pragma unroll
    for (int s = 0; s < DSN; s++) A[s] = -__expf(al[s]);
    float Dv = dd[(size_t)(layer*2+br)*DI + d];

    float h[DSN];
#pragma unroll
    for (int s = 0; s < DSN; s++) h[s] = 0.f;

    __shared__ float BC[32];
    for (int t = 0; t < LSEQ; t++) {
        __syncthreads();
        if (threadIdx.x < 32)
            BC[threadIdx.x] = g_dbl[br][((size_t)b*LSEQ + t)*80 + 48 + threadIdx.x];
        __syncthreads();
        size_t o = ((size_t)b*LSEQ + t)*DI + d;
        float dtv = g_dt[br][o];
        float u   = g_c[br][o];
        float du  = dtv * u;
        float acc = 0.f;
#pragma unroll
        for (int s = 0; s < DSN; s++) {
            float dA = __expf(dtv * A[s]);
            h[s] = fmaf(dA, h[s], du * BC[s]);
            acc  = fmaf(h[s], BC[16+s], acc);
        }
        g_c[br][o] = fmaf(u, Dv, acc);   // raw scan output (pre-z gating)
    }
}

// ---------------- combine: y = 0.5*silu(z)*(s_f[t] + s_b[L-1-t]) ----------
__global__ void k_combine()
{
    int idx = blockIdx.x * blockDim.x + threadIdx.x;
    if (idx >= BATCH*LSEQ*DI) return;
    int d = idx % DI;
    int t = (idx / DI) % LSEQ;
    int b = idx / (DI*LSEQ);
    float z  = g_xz[((size_t)b*LSEQ + t)*(2*DI) + DI + d];
    float s0 = g_c[0][((size_t)b*LSEQ + t)*DI + d];
    float s1 = g_c[1][((size_t)b*LSEQ + (LSEQ-1-t))*DI + d];
    g_y[((size_t)b*LSEQ + t)*DI + d] = 0.5f * siluf(z) * (s0 + s1);
}

// ---------------- final layernorm on token 0 ------------------------------
__global__ __launch_bounds__(256)
void k_final(const float* __restrict__ fn_w, const float* __restrict__ fn_b,
             float* __restrict__ out)
{
    int b = blockIdx.x;
    int tid = threadIdx.x;
    __shared__ float red[256];
    size_t base = (size_t)b * LSEQ * DM;   // token 0
    float v[3]; float s = 0.f;
#pragma unroll
    for (int i = 0; i < 3; i++) {
        int n = tid + i*256;
        float t = g_res[base+n] + g_h[base+n];
        v[i] = t; s += t;
    }
    red[tid] = s; __syncthreads();
    for (int o = 128; o > 0; o >>= 1) { if (tid < o) red[tid] += red[tid+o]; __syncthreads(); }
    float mean = red[0] / (float)DM;
    __syncthreads();
    s = 0.f;
#pragma unroll
    for (int i = 0; i < 3; i++) { float dv = v[i] - mean; s += dv*dv; }
    red[tid] = s; __syncthreads();
    for (int o = 128; o > 0; o >>= 1) { if (tid < o) red[tid] += red[tid+o]; __syncthreads(); }
    float inv = rsqrtf(red[0] / (float)DM + 1e-5f);
#pragma unroll
    for (int i = 0; i < 3; i++) {
        int n = tid + i*256;
        out[(size_t)b*DM + n] = (v[i] - mean) * inv * fn_w[n] + fn_b[n];
    }
}

// ---------------- host orchestration --------------------------------------
static float* symaddr(const void* sym)
{
    void* p = nullptr;
    cudaGetSymbolAddress(&p, sym);
    return (float*)p;
}

extern "C" void kernel_launch(void* const* d_in, const int* in_sizes, int n_in,
                              void* d_out, int out_size)
{
    const float* x        = (const float*)d_in[0];
    const float* patch_w  = (const float*)d_in[1];
    const float* patch_b  = (const float*)d_in[2];
    const float* cls_tok  = (const float*)d_in[3];
    const float* pos_emb  = (const float*)d_in[4];
    const float* ln_w     = (const float*)d_in[5];
    const float* w_in     = (const float*)d_in[6];
    const float* conv_w   = (const float*)d_in[7];
    const float* conv_b   = (const float*)d_in[8];
    const float* w_x      = (const float*)d_in[9];
    const float* w_dt     = (const float*)d_in[10];
    const float* b_dt     = (const float*)d_in[11];
    const float* a_log    = (const float*)d_in[12];
    const float* dd       = (const float*)d_in[13];
    const float* w_out    = (const float*)d_in[14];
    const float* fn_w     = (const float*)d_in[15];
    const float* fn_b     = (const float*)d_in[16];
    float* out = (float*)d_out;

    float* p_xn   = symaddr(g_xn);
    float* p_xz   = symaddr(g_xz);
    float* p_c    = symaddr(g_c);
    float* p_dbl  = symaddr(g_dbl);
    float* p_dt   = symaddr(g_dt);
    float* p_y    = symaddr(g_y);
    float* p_h    = symaddr(g_h);
    float* p_xp   = symaddr(g_xp);
    float* p_ptok = symaddr(g_ptok);

    // ---- patch embedding ----
    k_patchify<<<(BATCH*NPATCH*PDIM + 255)/256, 256>>>(x);
    gemm_nt<<<dim3((DM+127)/128, (BATCH*NPATCH+127)/128), 256>>>(
        p_xp, PDIM, patch_w, PDIM, p_ptok, DM, BATCH*NPATCH, DM, PDIM);
    k_assemble<<<(MTOK*DM + 255)/256, 256>>>(patch_b, cls_tok, pos_emb);

    // ---- 24 layers ----
    for (int layer = 0; layer < NDEPTH; layer++) {
        k_prenorm<<<MTOK, 256>>>(ln_w, layer);

        // in-projection: xz[2052,3072] = xn @ w_in^T
        gemm_nt<<<dim3((2*DI+127)/128, (MTOK+127)/128), 256>>>(
            p_xn, DM, w_in + (size_t)layer*2*DI*DM, DM, p_xz, 2*DI,
            MTOK, 2*DI, DM);

        k_conv<<<(BATCH*LSEQ*DI + 255)/256, 256>>>(conv_w, conv_b, layer);

        // x-projection (both branches): dbl[br][2052,80]
        k_gemm_x<<<dim3((MTOK+15)/16, 2), 256>>>(w_x, layer);

        // dt-projection as GEMM (K=48) then bias+softplus
        for (int br = 0; br < 2; br++) {
            gemm_nt<<<dim3((DI+127)/128, (MTOK+127)/128), 256>>>(
                p_dbl + (size_t)br*MTOK*80, 80,
                w_dt + (size_t)(layer*2+br)*DI*DTRK, DTRK,
                p_dt + (size_t)br*MTOK*DI, DI,
                MTOK, DI, DTRK);
        }
        k_softplus<<<dim3((MTOK*DI + 255)/256, 2), 256>>>(b_dt, layer);

        // selective scan (both branches, state in registers)
        k_scan<<<dim3(DI/128, BATCH, 2), 128>>>(a_log, dd, layer);

        // combine branches with silu(z) gate
        k_combine<<<(BATCH*LSEQ*DI + 255)/256, 256>>>();

        // out-projection: h[2052,768] = y @ w_out^T
        gemm_nt<<<dim3((DM+127)/128, (MTOK+127)/128), 256>>>(
            p_y, DI, w_out + (size_t)layer*DM*DI, DI, p_h, DM,
            MTOK, DM, DI);
    }

    // ---- final: layernorm((res + h)[:,0]) ----
    k_final<<<BATCH, 256>>>(fn_w, fn_b, out);
}

// round 2
// speedup vs baseline: 1.0064x; 1.0064x over previous
#include <cuda_runtime.h>
#include <math.h>
#include <stdint.h>

#define BATCH 4
#define LSEQ 513
#define MTOK (BATCH*LSEQ)      // 2052
#define DM 768
#define DI 1536
#define DSN 16
#define DTRK 48
#define NDEPTH 24
#define NPATCH 512
#define PDIM 256

// ---------------- scratch (device globals; no allocation allowed) ----------
__device__ float g_h  [MTOK*DM];
__device__ float g_res[MTOK*DM];
__device__ float g_xn [MTOK*DM];
__device__ float g_xz [MTOK*2*DI];
__device__ float g_c  [2][MTOK*DI];
__device__ float g_dbl[2][MTOK*80];
__device__ float g_dt [2][MTOK*DI];
__device__ float g_y  [MTOK*DI];
__device__ float g_xp [BATCH*NPATCH*PDIM];
__device__ float g_ptok[BATCH*NPATCH*DM];

__device__ __forceinline__ float siluf(float x){ return x / (1.f + __expf(-x)); }

// ---------------- tf32 helpers --------------------------------------------
__device__ __forceinline__ uint32_t f2tf32(float x){
    uint32_t r;
    asm("cvt.rna.tf32.f32 %0, %1;" : "=r"(r) : "f"(x));
    return r;
}
__device__ __forceinline__ void tf32split(float x, uint32_t& hi, uint32_t& lo){
    hi = f2tf32(x);
    float rem = x - __uint_as_float(hi);
    lo = f2tf32(rem);
}
__device__ __forceinline__ void mma8(float* d, const uint32_t* a, uint32_t b0, uint32_t b1){
    asm("mma.sync.aligned.m16n8k8.row.col.f32.tf32.tf32.f32 "
        "{%0,%1,%2,%3},{%4,%5,%6,%7},{%8,%9},{%0,%1,%2,%3};"
        : "+f"(d[0]), "+f"(d[1]), "+f"(d[2]), "+f"(d[3])
        : "r"(a[0]), "r"(a[1]), "r"(a[2]), "r"(a[3]), "r"(b0), "r"(b1));
}

// ---------------- tf32x3 tensor-core GEMM:  C[M,N] = A[M,K] * B[N,K]^T ----
// Row-major A (lda), B stored N x K row-major (ldb), row-major C (ldc).
// K % 16 == 0 required. Batched over blockIdx.z with given strides.
__global__ __launch_bounds__(256)
void gemm_tf32(const float* __restrict__ A0, int lda, size_t strideA,
               const float* __restrict__ B0, int ldb, size_t strideB,
               float* __restrict__ C0, int ldc, size_t strideC,
               int M, int N, int K)
{
    __shared__ float As[2][16][136];
    __shared__ float Bs[2][16][136];

    const float* A = A0 + strideA * blockIdx.z;
    const float* B = B0 + strideB * blockIdx.z;
    float*       C = C0 + strideC * blockIdx.z;

    const int tid  = threadIdx.x;
    const int lane = tid & 31;
    const int warp = tid >> 5;
    const int wm = warp & 3;       // 0..3 -> 32-row strip
    const int wn = warp >> 2;      // 0..1 -> 64-col strip
    const int g  = lane >> 2;      // group id 0..7
    const int cc = lane & 3;       // thread-in-group 0..3
    const int rowBase = blockIdx.y * 128;
    const int colBase = blockIdx.x * 128;

    float acc[2][8][4];
#pragma unroll
    for (int i = 0; i < 2; i++)
#pragma unroll
        for (int j = 0; j < 8; j++)
#pragma unroll
            for (int q = 0; q < 4; q++) acc[i][j][q] = 0.f;

    auto loadTile = [&](int buf, int k0){
#pragma unroll
        for (int it = 0; it < 2; it++) {
            int f  = tid + it * 256;          // 0..511
            int r  = f >> 2;                  // 0..127
            int kq = (f & 3) * 4;             // 0,4,8,12
            int gr = rowBase + r;
            float4 v = make_float4(0.f,0.f,0.f,0.f);
            if (gr < M) v = *(const float4*)&A[(size_t)gr*lda + k0 + kq];
            As[buf][kq+0][r]=v.x; As[buf][kq+1][r]=v.y;
            As[buf][kq+2][r]=v.z; As[buf][kq+3][r]=v.w;
        }
#pragma unroll
        for (int it = 0; it < 2; it++) {
            int f  = tid + it * 256;
            int r  = f >> 2;
            int kq = (f & 3) * 4;
            int gc = colBase + r;
            float4 v = make_float4(0.f,0.f,0.f,0.f);
            if (gc < N) v = *(const float4*)&B[(size_t)gc*ldb + k0 + kq];
            Bs[buf][kq+0][r]=v.x; Bs[buf][kq+1][r]=v.y;
            Bs[buf][kq+2][r]=v.z; Bs[buf][kq+3][r]=v.w;
        }
    };

    const int nk = K / 16;
    loadTile(0, 0);
    __syncthreads();

    for (int ks = 0; ks < nk; ks++) {
        int cur = ks & 1;
        if (ks + 1 < nk) loadTile(cur ^ 1, (ks + 1) * 16);

#pragma unroll
        for (int k8 = 0; k8 < 16; k8 += 8) {
            // A fragments (2 m-tiles), split into hi/lo
            uint32_t ah[2][4], al[2][4];
#pragma unroll
            for (int mt = 0; mt < 2; mt++) {
                int rb = wm*32 + mt*16;
                float a0 = As[cur][k8+cc  ][rb+g  ];
                float a1 = As[cur][k8+cc  ][rb+g+8];
                float a2 = As[cur][k8+4+cc][rb+g  ];
                float a3 = As[cur][k8+4+cc][rb+g+8];
                tf32split(a0, ah[mt][0], al[mt][0]);
                tf32split(a1, ah[mt][1], al[mt][1]);
                tf32split(a2, ah[mt][2], al[mt][2]);
                tf32split(a3, ah[mt][3], al[mt][3]);
            }
#pragma unroll
            for (int nt = 0; nt < 8; nt++) {
                int nb = wn*64 + nt*8;
                float b0 = Bs[cur][k8+cc  ][nb+g];
                float b1 = Bs[cur][k8+4+cc][nb+g];
                uint32_t bh0, bl0, bh1, bl1;
                tf32split(b0, bh0, bl0);
                tf32split(b1, bh1, bl1);
#pragma unroll
                for (int mt = 0; mt < 2; mt++) {
                    mma8(acc[mt][nt], ah[mt], bh0, bh1);  // hi*hi
                    mma8(acc[mt][nt], ah[mt], bl0, bl1);  // hi*lo
                    mma8(acc[mt][nt], al[mt], bh0, bh1);  // lo*hi
                }
            }
        }
        __syncthreads();
    }

    // epilogue
#pragma unroll
    for (int mt = 0; mt < 2; mt++) {
        int r0 = rowBase + wm*32 + mt*16 + g;
        int r1 = r0 + 8;
#pragma unroll
        for (int nt = 0; nt < 8; nt++) {
            int col = colBase + wn*64 + nt*8 + cc*2;
            if (col < N) {
                if (r0 < M) {
                    C[(size_t)r0*ldc + col    ] = acc[mt][nt][0];
                    C[(size_t)r0*ldc + col + 1] = acc[mt][nt][1];
                }
                if (r1 < M) {
                    C[(size_t)r1*ldc + col    ] = acc[mt][nt][2];
                    C[(size_t)r1*ldc + col + 1] = acc[mt][nt][3];
                }
            }
        }
    }
}

// ---------------- patchify: x(4,128,1024) -> xp(4,512,256) ----------------
__global__ void k_patchify(const float* __restrict__ x)
{
    int idx = blockIdx.x * blockDim.x + threadIdx.x;
    if (idx >= BATCH*NPATCH*PDIM) return;
    int i  = idx & 255;
    int p  = (idx >> 8) & 511;
    int b  = idx >> 17;
    int pr = i >> 4, pc = i & 15;
    int f  = p >> 6, t = p & 63;
    g_xp[idx] = x[((size_t)b*128 + f*16 + pr)*1024 + t*16 + pc];
}

// ---------------- assemble tokens: cls + patch_b + pos; res = 0 ----------
__global__ void k_assemble(const float* __restrict__ patch_b,
                           const float* __restrict__ cls,
                           const float* __restrict__ pos)
{
    int idx = blockIdx.x * blockDim.x + threadIdx.x;
    if (idx >= MTOK*DM) return;
    int n = idx % DM;
    int l = (idx / DM) % LSEQ;
    int b = idx / (DM*LSEQ);
    float v;
    if (l == 0) v = cls[n];
    else        v = g_ptok[((size_t)b*NPATCH + (l-1))*DM + n] + patch_b[n];
    v += pos[(size_t)l*DM + n];
    g_h[idx] = v;
    g_res[idx] = 0.f;
}

// ---------------- res += h;  xn = rmsnorm(res) * ln_w --------------------
__global__ __launch_bounds__(256)
void k_prenorm(const float* __restrict__ ln_w, int layer)
{
    int m = blockIdx.x;
    int tid = threadIdx.x;
    __shared__ float red[256];
    size_t base = (size_t)m * DM;
    float v[3]; float ss = 0.f;
#pragma unroll
    for (int i = 0; i < 3; i++) {
        int n = tid + i*256;
        float t = g_res[base+n] + g_h[base+n];
        v[i] = t; g_res[base+n] = t; ss += t*t;
    }
    red[tid] = ss; __syncthreads();
    for (int o = 128; o > 0; o >>= 1) { if (tid < o) red[tid] += red[tid+o]; __syncthreads(); }
    float scale = rsqrtf(red[0] / (float)DM + 1e-5f);
#pragma unroll
    for (int i = 0; i < 3; i++) {
        int n = tid + i*256;
        g_xn[base+n] = v[i] * scale * ln_w[(size_t)layer*DM + n];
    }
}

// ---------------- causal depthwise conv + silu (both branches) ------------
__global__ void k_conv(const float* __restrict__ conv_w,
                       const float* __restrict__ conv_b, int layer)
{
    int idx = blockIdx.x * blockDim.x + threadIdx.x;
    if (idx >= BATCH*LSEQ*DI) return;
    int d = idx % DI;
    int t = (idx / DI) % LSEQ;
    int b = idx / (DI*LSEQ);

    const float* w0 = conv_w + ((size_t)(layer*2+0)*DI + d)*4;
    const float* w1 = conv_w + ((size_t)(layer*2+1)*DI + d)*4;
    float acc0 = conv_b[(size_t)(layer*2+0)*DI + d];
    float acc1 = conv_b[(size_t)(layer*2+1)*DI + d];
#pragma unroll
    for (int k = 0; k < 4; k++) {
        int tt = t - 3 + k;
        if (tt >= 0) {
            acc0 = fmaf(w0[k], g_xz[((size_t)b*LSEQ + tt)*(2*DI) + d], acc0);
            acc1 = fmaf(w1[k], g_xz[((size_t)b*LSEQ + (LSEQ-1-tt))*(2*DI) + d], acc1);
        }
    }
    size_t o = ((size_t)b*LSEQ + t)*DI + d;
    g_c[0][o] = siluf(acc0);
    g_c[1][o] = siluf(acc1);
}

// ---------------- dt bias + softplus (in place on g_dt) -------------------
__global__ void k_softplus(const float* __restrict__ b_dt, int layer)
{
    int br = blockIdx.y;
    int idx = blockIdx.x * blockDim.x + threadIdx.x;
    if (idx >= MTOK*DI) return;
    int d = idx % DI;
    float x = g_dt[br][idx] + b_dt[(size_t)(layer*2+br)*DI + d];
    g_dt[br][idx] = (x > 20.f) ? x : log1pf(__expf(x));
}

// ---------------- selective scan (sequential over t), writes into g_c -----
__global__ __launch_bounds__(128)
void k_scan(const float* __restrict__ a_log,
            const float* __restrict__ dd, int layer)
{
    int br = blockIdx.z;
    int b  = blockIdx.y;
    int d  = blockIdx.x * 128 + threadIdx.x;

    const float* al = a_log + ((size_t)(layer*2+br)*DI + d)*DSN;
    float A[DSN];
#pragma unroll
    for (int s = 0; s < DSN; s++) A[s] = -__expf(al[s]);
    float Dv = dd[(size_t)(layer*2+br)*DI + d];

    float h[DSN];
#pragma unroll
    for (int s = 0; s < DSN; s++) h[s] = 0.f;

    __shared__ float BC[32];
    for (int t = 0; t < LSEQ; t++) {
        __syncthreads();
        if (threadIdx.x < 32)
            BC[threadIdx.x] = g_dbl[br][((size_t)b*LSEQ + t)*80 + 48 + threadIdx.x];
        __syncthreads();
        size_t o = ((size_t)b*LSEQ + t)*DI + d;
        float dtv = g_dt[br][o];
        float u   = g_c[br][o];
        float du  = dtv * u;
        float acc = 0.f;
#pragma unroll
        for (int s = 0; s < DSN; s++) {
            float dA = __expf(dtv * A[s]);
            h[s] = fmaf(dA, h[s], du * BC[s]);
            acc  = fmaf(h[s], BC[16+s], acc);
        }
        g_c[br][o] = fmaf(u, Dv, acc);   // raw scan output (pre-z gating)
    }
}

// ---------------- combine: y = 0.5*silu(z)*(s_f[t] + s_b[L-1-t]) ----------
__global__ void k_combine()
{
    int idx = blockIdx.x * blockDim.x + threadIdx.x;
    if (idx >= BATCH*LSEQ*DI) return;
    int d = idx % DI;
    int t = (idx / DI) % LSEQ;
    int b = idx / (DI*LSEQ);
    float z  = g_xz[((size_t)b*LSEQ + t)*(2*DI) + DI + d];
    float s0 = g_c[0][((size_t)b*LSEQ + t)*DI + d];
    float s1 = g_c[1][((size_t)b*LSEQ + (LSEQ-1-t))*DI + d];
    g_y[((size_t)b*LSEQ + t)*DI + d] = 0.5f * siluf(z) * (s0 + s1);
}

// ---------------- final layernorm on token 0 ------------------------------
__global__ __launch_bounds__(256)
void k_final(const float* __restrict__ fn_w, const float* __restrict__ fn_b,
             float* __restrict__ out)
{
    int b = blockIdx.x;
    int tid = threadIdx.x;
    __shared__ float red[256];
    size_t base = (size_t)b * LSEQ * DM;   // token 0
    float v[3]; float s = 0.f;
#pragma unroll
    for (int i = 0; i < 3; i++) {
        int n = tid + i*256;
        float t = g_res[base+n] + g_h[base+n];
        v[i] = t; s += t;
    }
    red[tid] = s; __syncthreads();
    for (int o = 128; o > 0; o >>= 1) { if (tid < o) red[tid] += red[tid+o]; __syncthreads(); }
    float mean = red[0] / (float)DM;
    __syncthreads();
    s = 0.f;
#pragma unroll
    for (int i = 0; i < 3; i++) { float dv = v[i] - mean; s += dv*dv; }
    red[tid] = s; __syncthreads();
    for (int o = 128; o > 0; o >>= 1) { if (tid < o) red[tid] += red[tid+o]; __syncthreads(); }
    float inv = rsqrtf(red[0] / (float)DM + 1e-5f);
#pragma unroll
    for (int i = 0; i < 3; i++) {
        int n = tid + i*256;
        out[(size_t)b*DM + n] = (v[i] - mean) * inv * fn_w[n] + fn_b[n];
    }
}

// ---------------- host orchestration --------------------------------------
static float* symaddr(const void* sym)
{
    void* p = nullptr;
    cudaGetSymbolAddress(&p, sym);
    return (float*)p;
}

extern "C" void kernel_launch(void* const* d_in, const int* in_sizes, int n_in,
                              void* d_out, int out_size)
{
    const float* x        = (const float*)d_in[0];
    const float* patch_w  = (const float*)d_in[1];
    const float* patch_b  = (const float*)d_in[2];
    const float* cls_tok  = (const float*)d_in[3];
    const float* pos_emb  = (const float*)d_in[4];
    const float* ln_w     = (const float*)d_in[5];
    const float* w_in     = (const float*)d_in[6];
    const float* conv_w   = (const float*)d_in[7];
    const float* conv_b   = (const float*)d_in[8];
    const float* w_x      = (const float*)d_in[9];
    const float* w_dt     = (const float*)d_in[10];
    const float* b_dt     = (const float*)d_in[11];
    const float* a_log    = (const float*)d_in[12];
    const float* dd       = (const float*)d_in[13];
    const float* w_out    = (const float*)d_in[14];
    const float* fn_w     = (const float*)d_in[15];
    const float* fn_b     = (const float*)d_in[16];
    float* out = (float*)d_out;

    float* p_xn   = symaddr(g_xn);
    float* p_xz   = symaddr(g_xz);
    float* p_c    = symaddr(g_c);
    float* p_dbl  = symaddr(g_dbl);
    float* p_dt   = symaddr(g_dt);
    float* p_y    = symaddr(g_y);
    float* p_h    = symaddr(g_h);
    float* p_xp   = symaddr(g_xp);
    float* p_ptok = symaddr(g_ptok);

    // ---- patch embedding ----
    k_patchify<<<(BATCH*NPATCH*PDIM + 255)/256, 256>>>(x);
    gemm_tf32<<<dim3((DM+127)/128, (BATCH*NPATCH+127)/128, 1), 256>>>(
        p_xp, PDIM, 0, patch_w, PDIM, 0, p_ptok, DM, 0,
        BATCH*NPATCH, DM, PDIM);
    k_assemble<<<(MTOK*DM + 255)/256, 256>>>(patch_b, cls_tok, pos_emb);

    // ---- 24 layers ----
    for (int layer = 0; layer < NDEPTH; layer++) {
        k_prenorm<<<MTOK, 256>>>(ln_w, layer);

        // in-projection: xz[2052,3072] = xn @ w_in^T
        gemm_tf32<<<dim3((2*DI+127)/128, (MTOK+127)/128, 1), 256>>>(
            p_xn, DM, 0, w_in + (size_t)layer*2*DI*DM, DM, 0,
            p_xz, 2*DI, 0, MTOK, 2*DI, DM);

        k_conv<<<(BATCH*LSEQ*DI + 255)/256, 256>>>(conv_w, conv_b, layer);

        // x-projection (both branches batched): dbl[br][2052,80] = c[br] @ w_x^T
        gemm_tf32<<<dim3(1, (MTOK+127)/128, 2), 256>>>(
            p_c, DI, (size_t)MTOK*DI,
            w_x + (size_t)layer*2*80*DI, DI, (size_t)80*DI,
            p_dbl, 80, (size_t)MTOK*80,
            MTOK, 80, DI);

        // dt-projection (both branches batched): dt[br][2052,1536]
        gemm_tf32<<<dim3((DI+127)/128, (MTOK+127)/128, 2), 256>>>(
            p_dbl, 80, (size_t)MTOK*80,
            w_dt + (size_t)layer*2*DI*DTRK, DTRK, (size_t)DI*DTRK,
            p_dt, DI, (size_t)MTOK*DI,
            MTOK, DI, DTRK);

        k_softplus<<<dim3((MTOK*DI + 255)/256, 2), 256>>>(b_dt, layer);

        // selective scan (both branches, state in registers)
        k_scan<<<dim3(DI/128, BATCH, 2), 128>>>(a_log, dd, layer);

        // combine branches with silu(z) gate
        k_combine<<<(BATCH*LSEQ*DI + 255)/256, 256>>>();

        // out-projection: h[2052,768] = y @ w_out^T
        gemm_tf32<<<dim3((DM+127)/128, (MTOK+127)/128, 1), 256>>>(
            p_y, DI, 0, w_out + (size_t)layer*DM*DI, DI, 0,
            p_h, DM, 0, MTOK, DM, DI);
    }

    // ---- final: layernorm((res + h)[:,0]) ----
    k_final<<<BATCH, 256>>>(fn_w, fn_b, out);
}

// round 3
// speedup vs baseline: 1.4503x; 1.4410x over previous
#include <cuda_runtime.h>
#include <cuda_bf16.h>
#include <math.h>
#include <stdint.h>

#define BATCH 4
#define LSEQ 513
#define MTOK (BATCH*LSEQ)      // 2052
#define DM 768
#define DI 1536
#define DSN 16
#define DTRK 48
#define NDEPTH 24
#define NPATCH 512
#define PDIM 256

// ---------------- scratch (device globals; no allocation allowed) ----------
__device__ float g_h  [MTOK*DM];
__device__ float g_res[MTOK*DM];
__device__ float g_xn [MTOK*DM];
__device__ float g_xz [MTOK*2*DI];
__device__ float g_c  [2][MTOK*DI];
__device__ float g_dbl[2][MTOK*80];
__device__ float g_dt [2][MTOK*DI];
__device__ float g_y  [MTOK*DI];
__device__ float g_xp [BATCH*NPATCH*PDIM];
__device__ float g_ptok[BATCH*NPATCH*DM];

__device__ __forceinline__ float siluf(float x){ return x / (1.f + __expf(-x)); }
__device__ __forceinline__ float ex2f(float x){
    float r; asm("ex2.approx.ftz.f32 %0, %1;" : "=f"(r) : "f"(x)); return r;
}

// pack two floats into bf16x2 (lo half = x, hi half = y), plus residual pack
__device__ __forceinline__ void split2(float x, float y, uint32_t& hi, uint32_t& lo){
    uint32_t h;
    asm("cvt.rn.bf16x2.f32 %0, %1, %2;" : "=r"(h) : "f"(y), "f"(x));
    float hx = __uint_as_float(h << 16);
    float hy = __uint_as_float(h & 0xffff0000u);
    float rx = x - hx;
    float ry = y - hy;
    uint32_t l;
    asm("cvt.rn.bf16x2.f32 %0, %1, %2;" : "=r"(l) : "f"(ry), "f"(rx));
    hi = h; lo = l;
}

__device__ __forceinline__ void mma16(float* d, const uint32_t* a, uint32_t b0, uint32_t b1){
    asm("mma.sync.aligned.m16n8k16.row.col.f32.bf16.bf16.f32 "
        "{%0,%1,%2,%3},{%4,%5,%6,%7},{%8,%9},{%0,%1,%2,%3};"
        : "+f"(d[0]), "+f"(d[1]), "+f"(d[2]), "+f"(d[3])
        : "r"(a[0]), "r"(a[1]), "r"(a[2]), "r"(a[3]), "r"(b0), "r"(b1));
}

// ---------------- bf16x3 tensor-core GEMM:  C[M,N] = A[M,K] * B[N,K]^T ----
// Row-major A (lda), B stored N x K row-major (ldb), row-major C (ldc).
// K % 16 == 0. Batched over blockIdx.z. Optional epilogue: bias + softplus.
__global__ __launch_bounds__(256, 2)
void gemm_bf3(const float* __restrict__ A0, int lda, size_t strideA,
              const float* __restrict__ B0, int ldb, size_t strideB,
              float* __restrict__ C0, int ldc, size_t strideC,
              int M, int N, int K,
              const float* __restrict__ ep_bias, int ep_stride)
{
    // bf16x2-packed planes: [k-pair 0..7][row/col 0..127] stride 136 (≡8 mod 32)
    __shared__ uint32_t Ah[2][8][136], Al[2][8][136];
    __shared__ uint32_t Bh[2][8][136], Bl[2][8][136];

    const float* A = A0 + strideA * blockIdx.z;
    const float* B = B0 + strideB * blockIdx.z;
    float*       C = C0 + strideC * blockIdx.z;

    const int tid  = threadIdx.x;
    const int lane = tid & 31;
    const int warp = tid >> 5;
    const int wm = warp & 3;       // 32-row strip
    const int wn = warp >> 2;      // 64-col strip
    const int g  = lane >> 2;
    const int cc = lane & 3;
    const int rowBase = blockIdx.y * 128;
    const int colBase = blockIdx.x * 128;

    float acc[2][8][4];
#pragma unroll
    for (int i = 0; i < 2; i++)
#pragma unroll
        for (int j = 0; j < 8; j++)
#pragma unroll
            for (int q = 0; q < 4; q++) acc[i][j][q] = 0.f;

    auto loadTile = [&](int buf, int k0){
#pragma unroll
        for (int it = 0; it < 2; it++) {
            int f  = tid + it * 256;          // 0..511
            int r  = f >> 2;                  // 0..127
            int kq = (f & 3) * 4;             // 0,4,8,12
            int jp = kq >> 1;                 // pair index 0,2,4,6
            int gr = rowBase + r;
            float4 v = make_float4(0.f,0.f,0.f,0.f);
            if (gr < M) v = *(const float4*)&A[(size_t)gr*lda + k0 + kq];
            uint32_t h01,l01,h23,l23;
            split2(v.x, v.y, h01, l01);
            split2(v.z, v.w, h23, l23);
            Ah[buf][jp  ][r] = h01; Al[buf][jp  ][r] = l01;
            Ah[buf][jp+1][r] = h23; Al[buf][jp+1][r] = l23;
        }
#pragma unroll
        for (int it = 0; it < 2; it++) {
            int f  = tid + it * 256;
            int r  = f >> 2;
            int kq = (f & 3) * 4;
            int jp = kq >> 1;
            int gc = colBase + r;
            float4 v = make_float4(0.f,0.f,0.f,0.f);
            if (gc < N) v = *(const float4*)&B[(size_t)gc*ldb + k0 + kq];
            uint32_t h01,l01,h23,l23;
            split2(v.x, v.y, h01, l01);
            split2(v.z, v.w, h23, l23);
            Bh[buf][jp  ][r] = h01; Bl[buf][jp  ][r] = l01;
            Bh[buf][jp+1][r] = h23; Bl[buf][jp+1][r] = l23;
        }
    };

    const int nk = K / 16;
    loadTile(0, 0);
    __syncthreads();

    for (int ks = 0; ks < nk; ks++) {
        int cur = ks & 1;
        if (ks + 1 < nk) loadTile(cur ^ 1, (ks + 1) * 16);

        // A fragments for both m-tiles, hi and lo
        uint32_t ah[2][4], al[2][4];
#pragma unroll
        for (int mt = 0; mt < 2; mt++) {
            int rb = wm*32 + mt*16;
            ah[mt][0] = Ah[cur][cc  ][rb+g  ];
            ah[mt][1] = Ah[cur][cc  ][rb+g+8];
            ah[mt][2] = Ah[cur][cc+4][rb+g  ];
            ah[mt][3] = Ah[cur][cc+4][rb+g+8];
            al[mt][0] = Al[cur][cc  ][rb+g  ];
            al[mt][1] = Al[cur][cc  ][rb+g+8];
            al[mt][2] = Al[cur][cc+4][rb+g  ];
            al[mt][3] = Al[cur][cc+4][rb+g+8];
        }
#pragma unroll
        for (int nt = 0; nt < 8; nt++) {
            int nb = wn*64 + nt*8;
            uint32_t bh0 = Bh[cur][cc  ][nb+g];
            uint32_t bh1 = Bh[cur][cc+4][nb+g];
            uint32_t bl0 = Bl[cur][cc  ][nb+g];
            uint32_t bl1 = Bl[cur][cc+4][nb+g];
#pragma unroll
            for (int mt = 0; mt < 2; mt++) {
                mma16(acc[mt][nt], ah[mt], bh0, bh1);   // hi*hi
                mma16(acc[mt][nt], ah[mt], bl0, bl1);   // hi*lo
                mma16(acc[mt][nt], al[mt], bh0, bh1);   // lo*hi
            }
        }
        __syncthreads();
    }

    // epilogue (optional bias + softplus)
#pragma unroll
    for (int mt = 0; mt < 2; mt++) {
        int r0 = rowBase + wm*32 + mt*16 + g;
        int r1 = r0 + 8;
#pragma unroll
        for (int nt = 0; nt < 8; nt++) {
            int col = colBase + wn*64 + nt*8 + cc*2;
            if (col >= N) continue;
            float v0 = acc[mt][nt][0], v1 = acc[mt][nt][1];
            float v2 = acc[mt][nt][2], v3 = acc[mt][nt][3];
            if (ep_bias) {
                float b0 = ep_bias[(size_t)ep_stride*blockIdx.z + col];
                float b1 = ep_bias[(size_t)ep_stride*blockIdx.z + col + 1];
                v0 += b0; v1 += b1; v2 += b0; v3 += b1;
                v0 = (v0 > 20.f) ? v0 : log1pf(__expf(v0));
                v1 = (v1 > 20.f) ? v1 : log1pf(__expf(v1));
                v2 = (v2 > 20.f) ? v2 : log1pf(__expf(v2));
                v3 = (v3 > 20.f) ? v3 : log1pf(__expf(v3));
            }
            if (r0 < M) { C[(size_t)r0*ldc + col] = v0; C[(size_t)r0*ldc + col + 1] = v1; }
            if (r1 < M) { C[(size_t)r1*ldc + col] = v2; C[(size_t)r1*ldc + col + 1] = v3; }
        }
    }
}

// ---------------- patchify: x(4,128,1024) -> xp(4,512,256) ----------------
__global__ void k_patchify(const float* __restrict__ x)
{
    int idx = blockIdx.x * blockDim.x + threadIdx.x;
    if (idx >= BATCH*NPATCH*PDIM) return;
    int i  = idx & 255;
    int p  = (idx >> 8) & 511;
    int b  = idx >> 17;
    int pr = i >> 4, pc = i & 15;
    int f  = p >> 6, t = p & 63;
    g_xp[idx] = x[((size_t)b*128 + f*16 + pr)*1024 + t*16 + pc];
}

// ---------------- assemble tokens: cls + patch_b + pos; res = 0 ----------
__global__ void k_assemble(const float* __restrict__ patch_b,
                           const float* __restrict__ cls,
                           const float* __restrict__ pos)
{
    int idx = blockIdx.x * blockDim.x + threadIdx.x;
    if (idx >= MTOK*DM) return;
    int n = idx % DM;
    int l = (idx / DM) % LSEQ;
    int b = idx / (DM*LSEQ);
    float v;
    if (l == 0) v = cls[n];
    else        v = g_ptok[((size_t)b*NPATCH + (l-1))*DM + n] + patch_b[n];
    v += pos[(size_t)l*DM + n];
    g_h[idx] = v;
    g_res[idx] = 0.f;
}

// ---------------- res += h;  xn = rmsnorm(res) * ln_w --------------------
__global__ __launch_bounds__(256)
void k_prenorm(const float* __restrict__ ln_w, int layer)
{
    int m = blockIdx.x;
    int tid = threadIdx.x;
    __shared__ float red[256];
    size_t base = (size_t)m * DM;
    float v[3]; float ss = 0.f;
#pragma unroll
    for (int i = 0; i < 3; i++) {
        int n = tid + i*256;
        float t = g_res[base+n] + g_h[base+n];
        v[i] = t; g_res[base+n] = t; ss += t*t;
    }
    red[tid] = ss; __syncthreads();
    for (int o = 128; o > 0; o >>= 1) { if (tid < o) red[tid] += red[tid+o]; __syncthreads(); }
    float scale = rsqrtf(red[0] / (float)DM + 1e-5f);
#pragma unroll
    for (int i = 0; i < 3; i++) {
        int n = tid + i*256;
        g_xn[base+n] = v[i] * scale * ln_w[(size_t)layer*DM + n];
    }
}

// ---------------- causal depthwise conv + silu (both branches) ------------
__global__ void k_conv(const float* __restrict__ conv_w,
                       const float* __restrict__ conv_b, int layer)
{
    int idx = blockIdx.x * blockDim.x + threadIdx.x;
    if (idx >= BATCH*LSEQ*DI) return;
    int d = idx % DI;
    int t = (idx / DI) % LSEQ;
    int b = idx / (DI*LSEQ);

    const float* w0 = conv_w + ((size_t)(layer*2+0)*DI + d)*4;
    const float* w1 = conv_w + ((size_t)(layer*2+1)*DI + d)*4;
    float acc0 = conv_b[(size_t)(layer*2+0)*DI + d];
    float acc1 = conv_b[(size_t)(layer*2+1)*DI + d];
#pragma unroll
    for (int k = 0; k < 4; k++) {
        int tt = t - 3 + k;
        if (tt >= 0) {
            acc0 = fmaf(w0[k], g_xz[((size_t)b*LSEQ + tt)*(2*DI) + d], acc0);
            acc1 = fmaf(w1[k], g_xz[((size_t)b*LSEQ + (LSEQ-1-tt))*(2*DI) + d], acc1);
        }
    }
    size_t o = ((size_t)b*LSEQ + t)*DI + d;
    g_c[0][o] = siluf(acc0);
    g_c[1][o] = siluf(acc1);
}

// ---------------- selective scan (no barriers, shfl broadcast, prefetch) --
__global__ __launch_bounds__(128)
void k_scan(const float* __restrict__ a_log,
            const float* __restrict__ dd, int layer)
{
    int br = blockIdx.z;
    int b  = blockIdx.y;
    int d  = blockIdx.x * 128 + threadIdx.x;
    int lane = threadIdx.x & 31;

    const float* al = a_log + ((size_t)(layer*2+br)*DI + d)*DSN;
    float A2[DSN];
#pragma unroll
    for (int s = 0; s < DSN; s++) A2[s] = -__expf(al[s]) * 1.44269504f;
    float Dv = dd[(size_t)(layer*2+br)*DI + d];

    float h[DSN];
#pragma unroll
    for (int s = 0; s < DSN; s++) h[s] = 0.f;

    const float* dblp = &g_dbl[br][(size_t)b*LSEQ*80 + 48];
    const float* dtp  = &g_dt[br][(size_t)b*LSEQ*DI + d];
    float*       cp   = &g_c [br][(size_t)b*LSEQ*DI + d];

    // prefetch pipeline depth 2
    float bc0 = dblp[lane];
    float dt0 = dtp[0];
    float u0  = cp[0];
    float bc1 = dblp[80 + lane];
    float dt1 = dtp[DI];
    float u1  = cp[DI];

    for (int t = 0; t < LSEQ; t++) {
        float bc = bc0, dtv = dt0, u = u0;
        bc0 = bc1; dt0 = dt1; u0 = u1;
        if (t + 2 < LSEQ) {
            bc1 = dblp[(t+2)*80 + lane];
            dt1 = dtp[(size_t)(t+2)*DI];
            u1  = cp [(size_t)(t+2)*DI];
        }
        float du  = dtv * u;
        float acc = 0.f;
#pragma unroll
        for (int s = 0; s < DSN; s++) {
            float Bs = __shfl_sync(0xffffffffu, bc, s);
            float Cs = __shfl_sync(0xffffffffu, bc, 16 + s);
            float dA = ex2f(dtv * A2[s]);
            h[s] = fmaf(dA, h[s], du * Bs);
            acc  = fmaf(h[s], Cs, acc);
        }
        cp[(size_t)t*DI] = fmaf(u, Dv, acc);   // raw scan output (pre-z gating)
    }
}

// ---------------- combine: y = 0.5*silu(z)*(s_f[t] + s_b[L-1-t]) ----------
__global__ void k_combine()
{
    int idx = blockIdx.x * blockDim.x + threadIdx.x;
    if (idx >= BATCH*LSEQ*DI) return;
    int d = idx % DI;
    int t = (idx / DI) % LSEQ;
    int b = idx / (DI*LSEQ);
    float z  = g_xz[((size_t)b*LSEQ + t)*(2*DI) + DI + d];
    float s0 = g_c[0][((size_t)b*LSEQ + t)*DI + d];
    float s1 = g_c[1][((size_t)b*LSEQ + (LSEQ-1-t))*DI + d];
    g_y[((size_t)b*LSEQ + t)*DI + d] = 0.5f * siluf(z) * (s0 + s1);
}

// ---------------- final layernorm on token 0 ------------------------------
__global__ __launch_bounds__(256)
void k_final(const float* __restrict__ fn_w, const float* __restrict__ fn_b,
             float* __restrict__ out)
{
    int b = blockIdx.x;
    int tid = threadIdx.x;
    __shared__ float red[256];
    size_t base = (size_t)b * LSEQ * DM;   // token 0
    float v[3]; float s = 0.f;
#pragma unroll
    for (int i = 0; i < 3; i++) {
        int n = tid + i*256;
        float t = g_res[base+n] + g_h[base+n];
        v[i] = t; s += t;
    }
    red[tid] = s; __syncthreads();
    for (int o = 128; o > 0; o >>= 1) { if (tid < o) red[tid] += red[tid+o]; __syncthreads(); }
    float mean = red[0] / (float)DM;
    __syncthreads();
    s = 0.f;
#pragma unroll
    for (int i = 0; i < 3; i++) { float dv = v[i] - mean; s += dv*dv; }
    red[tid] = s; __syncthreads();
    for (int o = 128; o > 0; o >>= 1) { if (tid < o) red[tid] += red[tid+o]; __syncthreads(); }
    float inv = rsqrtf(red[0] / (float)DM + 1e-5f);
#pragma unroll
    for (int i = 0; i < 3; i++) {
        int n = tid + i*256;
        out[(size_t)b*DM + n] = (v[i] - mean) * inv * fn_w[n] + fn_b[n];
    }
}

// ---------------- host orchestration --------------------------------------
static float* symaddr(const void* sym)
{
    void* p = nullptr;
    cudaGetSymbolAddress(&p, sym);
    return (float*)p;
}

extern "C" void kernel_launch(void* const* d_in, const int* in_sizes, int n_in,
                              void* d_out, int out_size)
{
    const float* x        = (const float*)d_in[0];
    const float* patch_w  = (const float*)d_in[1];
    const float* patch_b  = (const float*)d_in[2];
    const float* cls_tok  = (const float*)d_in[3];
    const float* pos_emb  = (const float*)d_in[4];
    const float* ln_w     = (const float*)d_in[5];
    const float* w_in     = (const float*)d_in[6];
    const float* conv_w   = (const float*)d_in[7];
    const float* conv_b   = (const float*)d_in[8];
    const float* w_x      = (const float*)d_in[9];
    const float* w_dt     = (const float*)d_in[10];
    const float* b_dt     = (const float*)d_in[11];
    const float* a_log    = (const float*)d_in[12];
    const float* dd       = (const float*)d_in[13];
    const float* w_out    = (const float*)d_in[14];
    const float* fn_w     = (const float*)d_in[15];
    const float* fn_b     = (const float*)d_in[16];
    float* out = (float*)d_out;

    float* p_xn   = symaddr(g_xn);
    float* p_xz   = symaddr(g_xz);
    float* p_c    = symaddr(g_c);
    float* p_dbl  = symaddr(g_dbl);
    float* p_dt   = symaddr(g_dt);
    float* p_y    = symaddr(g_y);
    float* p_h    = symaddr(g_h);
    float* p_xp   = symaddr(g_xp);
    float* p_ptok = symaddr(g_ptok);

    // ---- patch embedding ----
    k_patchify<<<(BATCH*NPATCH*PDIM + 255)/256, 256>>>(x);
    gemm_bf3<<<dim3((DM+127)/128, (BATCH*NPATCH+127)/128, 1), 256>>>(
        p_xp, PDIM, 0, patch_w, PDIM, 0, p_ptok, DM, 0,
        BATCH*NPATCH, DM, PDIM, nullptr, 0);
    k_assemble<<<(MTOK*DM + 255)/256, 256>>>(patch_b, cls_tok, pos_emb);

    // ---- 24 layers ----
    for (int layer = 0; layer < NDEPTH; layer++) {
        k_prenorm<<<MTOK, 256>>>(ln_w, layer);

        // in-projection: xz[2052,3072] = xn @ w_in^T
        gemm_bf3<<<dim3((2*DI+127)/128, (MTOK+127)/128, 1), 256>>>(
            p_xn, DM, 0, w_in + (size_t)layer*2*DI*DM, DM, 0,
            p_xz, 2*DI, 0, MTOK, 2*DI, DM, nullptr, 0);

        k_conv<<<(BATCH*LSEQ*DI + 255)/256, 256>>>(conv_w, conv_b, layer);

        // x-projection (both branches batched): dbl[br][2052,80] = c[br] @ w_x^T
        gemm_bf3<<<dim3(1, (MTOK+127)/128, 2), 256>>>(
            p_c, DI, (size_t)MTOK*DI,
            w_x + (size_t)layer*2*80*DI, DI, (size_t)80*DI,
            p_dbl, 80, (size_t)MTOK*80,
            MTOK, 80, DI, nullptr, 0);

        // dt-projection (both branches batched) with fused bias+softplus
        gemm_bf3<<<dim3((DI+127)/128, (MTOK+127)/128, 2), 256>>>(
            p_dbl, 80, (size_t)MTOK*80,
            w_dt + (size_t)layer*2*DI*DTRK, DTRK, (size_t)DI*DTRK,
            p_dt, DI, (size_t)MTOK*DI,
            MTOK, DI, DTRK,
            b_dt + (size_t)layer*2*DI, DI);

        // selective scan (both branches, state in registers)
        k_scan<<<dim3(DI/128, BATCH, 2), 128>>>(a_log, dd, layer);

        // combine branches with silu(z) gate
        k_combine<<<(BATCH*LSEQ*DI + 255)/256, 256>>>();

        // out-projection: h[2052,768] = y @ w_out^T
        gemm_bf3<<<dim3((DM+127)/128, (MTOK+127)/128, 1), 256>>>(
            p_y, DI, 0, w_out + (size_t)layer*DM*DI, DI, 0,
            p_h, DM, 0, MTOK, DM, DI, nullptr, 0);
    }

    // ---- final: layernorm((res + h)[:,0]) ----
    k_final<<<BATCH, 256>>>(fn_w, fn_b, out);
}